// round 5
// baseline (speedup 1.0000x reference)
#include <cuda_runtime.h>

// Problem constants (from reference): N=50000 nodes, E=800000 edges,
// 8 heads x 32 head_dim keys, value rows of 256 floats (64 ch x 4 rep).
#define MAX_N 50000
#define MAX_E 800000

// Scratch (allocation-free rule: __device__ globals)
__device__ int g_count[MAX_N];
__device__ int g_off[MAX_N + 1];
__device__ int g_pos[MAX_N];
__device__ int g_eid[MAX_E];

__global__ void zero_counts(int n_nodes) {
    int i = blockIdx.x * blockDim.x + threadIdx.x;
    if (i < n_nodes) g_count[i] = 0;
}

__global__ void histogram_kernel(const int* __restrict__ dst, int n_edges) {
    int i = blockIdx.x * blockDim.x + threadIdx.x;
    if (i < n_edges) atomicAdd(&g_count[dst[i]], 1);
}

// Single-block exclusive scan over g_count -> g_off, g_pos. 1024 threads.
__global__ void scan_offsets(int n_nodes) {
    __shared__ int warp_incl[32];
    __shared__ int s_carry;
    int tid = threadIdx.x, lane = tid & 31, wid = tid >> 5;
    if (tid == 0) s_carry = 0;
    __syncthreads();
    int nt = (n_nodes + 1023) & ~1023;
    for (int base = 0; base < nt; base += 1024) {
        int i = base + tid;
        int v = (i < n_nodes) ? g_count[i] : 0;
        int x = v;
        #pragma unroll
        for (int d2 = 1; d2 < 32; d2 <<= 1) {
            int y = __shfl_up_sync(0xffffffffu, x, d2);
            if (lane >= d2) x += y;
        }
        if (lane == 31) warp_incl[wid] = x;
        __syncthreads();
        if (wid == 0) {
            int s = warp_incl[lane];
            #pragma unroll
            for (int d2 = 1; d2 < 32; d2 <<= 1) {
                int y = __shfl_up_sync(0xffffffffu, s, d2);
                if (lane >= d2) s += y;
            }
            warp_incl[lane] = s;
        }
        __syncthreads();
        int warp_base = (wid > 0) ? warp_incl[wid - 1] : 0;
        int excl = s_carry + warp_base + (x - v);
        if (i < n_nodes) { g_off[i] = excl; g_pos[i] = excl; }
        int tile_total = warp_incl[31];
        __syncthreads();
        if (tid == 0) s_carry += tile_total;
        __syncthreads();
    }
    if (tid == 0) g_off[n_nodes] = s_carry;
}

__global__ void scatter_edges(const int* __restrict__ dst, int n_edges) {
    int i = blockIdx.x * blockDim.x + threadIdx.x;
    if (i < n_edges) {
        int p = atomicAdd(&g_pos[dst[i]], 1);
        g_eid[p] = i;
    }
}

// Fused attention: one block (256 threads) per node, one warp per head.
// Warps are fully independent: each warp owns s_ex[w][*] and q_sm[w][*].
__global__ void __launch_bounds__(256, 6) attn_kernel(
    const float* __restrict__ key_edge,   // [E, 8, 32]
    const float* __restrict__ q0,         // [N, 64, 1]
    const float* __restrict__ q1,         // [N, 64, 3]
    const float* __restrict__ value,      // [E, 64, 4] == [E, 256]
    float* __restrict__ out)              // [N, 64, 4] == [N, 256]
{
    constexpr int CH = 128;               // edges per softmax chunk
    __shared__ float s_ex[8][CH];
    __shared__ float q_sm[8][32];

    const int n    = blockIdx.x;
    const int tid  = threadIdx.x;
    const int w    = tid >> 5;            // head == warp id
    const int lane = tid & 31;
    const float NEG_INF = __int_as_float(0xff800000);

    // Build q[n, w, lane]: flat (64,4) index = w*32 + lane -> channel, rep
    {
        int c = (w << 3) + (lane >> 2);
        int r = lane & 3;
        float qv = (r == 0) ? __ldg(&q0[n * 64 + c])
                            : __ldg(&q1[(n * 64 + c) * 3 + (r - 1)]);
        q_sm[w][lane] = qv;
    }
    __syncwarp();

    const int beg = g_off[n];
    const int deg = g_off[n + 1] - beg;

    float acc   = 0.f;
    float m_run = NEG_INF;
    float l_run = 0.f;
    const float4* qp = reinterpret_cast<const float4*>(q_sm[w]);

    for (int base = 0; base < deg; base += CH) {
        const int cnt = min(CH, deg - base);
        const int* ep = &g_eid[beg + base];

        // ---- Pass A: scores, lane-per-edge (in-lane dot, 8x LDG.128 MLP) ----
        float mloc = NEG_INF;
        for (int i0 = 0; i0 < cnt; i0 += 32) {
            int idx = i0 + lane;
            if (idx < cnt) {
                int e = __ldg(&ep[idx]);
                const float4* kp = reinterpret_cast<const float4*>(
                    key_edge + ((size_t)e * 8 + w) * 32);
                float s = 0.f;
                #pragma unroll
                for (int j = 0; j < 8; j++) {
                    float4 k4 = __ldg(kp + j);
                    float4 q4 = qp[j];
                    s += k4.x * q4.x + k4.y * q4.y + k4.z * q4.z + k4.w * q4.w;
                }
                s *= 0.0625f;                 // 1/sqrt(256)
                s_ex[w][idx] = s;
                mloc = fmaxf(mloc, s);
            }
        }
        #pragma unroll
        for (int d2 = 16; d2 >= 1; d2 >>= 1)
            mloc = fmaxf(mloc, __shfl_xor_sync(0xffffffffu, mloc, d2));

        // ---- online-softmax chunk combine ----
        float m_new   = fmaxf(m_run, mloc);
        float rescale = __expf(m_run - m_new);   // 0 on first chunk
        acc   *= rescale;
        l_run *= rescale;
        __syncwarp();

        float lsum = 0.f;
        for (int i = lane; i < cnt; i += 32) {
            float ex = __expf(s_ex[w][i] - m_new);
            s_ex[w][i] = ex;
            lsum += ex;
        }
        #pragma unroll
        for (int d2 = 16; d2 >= 1; d2 >>= 1)
            lsum += __shfl_xor_sync(0xffffffffu, lsum, d2);
        l_run += lsum;
        m_run = m_new;
        __syncwarp();

        // ---- Pass B: weighted value accumulation (4-way unrolled MLP) ----
        int i = 0;
        for (; i + 4 <= cnt; i += 4) {
            int e0 = __ldg(&ep[i + 0]);
            int e1 = __ldg(&ep[i + 1]);
            int e2 = __ldg(&ep[i + 2]);
            int e3 = __ldg(&ep[i + 3]);
            float x0 = s_ex[w][i + 0];
            float x1 = s_ex[w][i + 1];
            float x2 = s_ex[w][i + 2];
            float x3 = s_ex[w][i + 3];
            float v0 = __ldg(&value[(size_t)e0 * 256 + tid]);
            float v1 = __ldg(&value[(size_t)e1 * 256 + tid]);
            float v2 = __ldg(&value[(size_t)e2 * 256 + tid]);
            float v3 = __ldg(&value[(size_t)e3 * 256 + tid]);
            acc = fmaf(x0, v0, acc);
            acc = fmaf(x1, v1, acc);
            acc = fmaf(x2, v2, acc);
            acc = fmaf(x3, v3, acc);
        }
        for (; i < cnt; i++) {
            int e = __ldg(&ep[i]);
            acc = fmaf(s_ex[w][i], __ldg(&value[(size_t)e * 256 + tid]), acc);
        }
        __syncwarp();
    }

    float o = (l_run > 0.f) ? acc * (1.f / l_run) : 0.f;
    out[(size_t)n * 256 + tid] = o;
}

extern "C" void kernel_launch(void* const* d_in, const int* in_sizes, int n_in,
                              void* d_out, int out_size) {
    const float* key_edge = (const float*)d_in[0];   // [E,8,32]
    const float* q0       = (const float*)d_in[1];   // [N,64,1]
    const float* q1       = (const float*)d_in[2];   // [N,64,3]
    const float* value    = (const float*)d_in[3];   // [E,64,4]
    const int*   dst      = (const int*)d_in[4];     // [E]

    int n_edges = in_sizes[4];
    int n_nodes = in_sizes[1] / 64;

    zero_counts<<<(n_nodes + 255) / 256, 256>>>(n_nodes);
    histogram_kernel<<<(n_edges + 255) / 256, 256>>>(dst, n_edges);
    scan_offsets<<<1, 1024>>>(n_nodes);
    scatter_edges<<<(n_edges + 255) / 256, 256>>>(dst, n_edges);
    attn_kernel<<<n_nodes, 256>>>(key_edge, q0, q1, value, (float*)d_out);
}